// round 17
// baseline (speedup 1.0000x reference)
#include <cuda_runtime.h>
#include <cuda_bf16.h>
#include <math.h>
#include <stdint.h>

// Problem constants
#define BATCH   4
#define SEQ     2048
#define DMODEL  1024
#define NHEAD   16
#define HDIM    64
#define ROWS    (BATCH * SEQ)          // 8192

#if defined(__CUDA_ARCH_FEAT_SM103_ALL) || defined(__CUDA_ARCH_FEAT_SM100_ALL)
#define HAS_TCGEN05 1
#else
#define HAS_TCGEN05 0
#endif

// -------- scratch (static device globals; no allocation allowed) ----------
__device__ float         g_Y[ROWS * DMODEL];          // Y = O + X (pre-LN)
__device__ __nv_bfloat16 g_Xbf[ROWS * DMODEL];
__device__ __nv_bfloat16 g_AObf[ROWS * DMODEL];
__device__ __nv_bfloat16 g_Qhi[ROWS * DMODEL];
__device__ __nv_bfloat16 g_Kbf[ROWS * DMODEL];
__device__ __nv_bfloat16 g_VT[BATCH * NHEAD * HDIM * SEQ]; // V^T: [bh][d][key]
__device__ __nv_bfloat16 g_Wqb[DMODEL * DMODEL];
__device__ __nv_bfloat16 g_Wkb[DMODEL * DMODEL];
__device__ __nv_bfloat16 g_Wvb[DMODEL * DMODEL];
__device__ __nv_bfloat16 g_Wob[DMODEL * DMODEL];

// ===========================================================================
// PTX helpers
// ===========================================================================
__device__ __forceinline__ uint32_t smem_u32(const void* p) {
    uint32_t a;
    asm("{ .reg .u64 t; cvta.to.shared.u64 t, %1; cvt.u32.u64 %0, t; }" : "=r"(a) : "l"(p));
    return a;
}
__device__ __forceinline__ uint32_t elect_one() {
    uint32_t p;
    asm volatile("{ .reg .pred q; elect.sync _|q, 0xFFFFFFFF; selp.b32 %0, 1, 0, q; }" : "=r"(p));
    return p;
}
__device__ __forceinline__ void mbar_init(uint32_t mbar, uint32_t cnt) {
    asm volatile("mbarrier.init.shared.b64 [%0], %1;" :: "r"(mbar), "r"(cnt) : "memory");
}
__device__ __forceinline__ void mbar_wait(uint32_t mbar, uint32_t parity) {
    uint32_t done;
    asm volatile("{ .reg .pred p; mbarrier.try_wait.parity.acquire.cta.shared::cta.b64 p, [%1], %2; selp.b32 %0, 1, 0, p; }"
                 : "=r"(done) : "r"(mbar), "r"(parity) : "memory");
    while (!done) {
        asm volatile("{ .reg .pred p; mbarrier.try_wait.parity.acquire.cta.shared::cta.b64 p, [%1], %2, 0x989680; selp.b32 %0, 1, 0, p; }"
                     : "=r"(done) : "r"(mbar), "r"(parity) : "memory");
    }
}
__device__ __forceinline__ void fence_proxy_async_shared() { asm volatile("fence.proxy.async.shared::cta;" ::: "memory"); }

__device__ __forceinline__ void cp16(uint32_t dst, const void* src) {
    asm volatile("cp.async.cg.shared.global [%0], [%1], 16;" :: "r"(dst), "l"(src) : "memory");
}
#define CP_COMMIT() asm volatile("cp.async.commit_group;" ::: "memory")
#define CP_WAIT(n)  asm volatile("cp.async.wait_group %0;" :: "n"(n) : "memory")

__device__ __forceinline__ float fast_ex2(float x) {
    float r;
    asm("ex2.approx.f32 %0, %1;" : "=f"(r) : "f"(x));
    return r;
}

// SW128 K-major smem descriptor
static constexpr uint64_t DESC_BASE_SW128 =
    (uint64_t(2) << 61) | (uint64_t(1) << 46) | (uint64_t(64) << 32) | (uint64_t(1) << 16);
__device__ __forceinline__ uint64_t make_desc(uint32_t addr) {
    return DESC_BASE_SW128 | ((uint64_t)(addr >> 4) & 0x3FFF);
}

#if HAS_TCGEN05
__device__ __forceinline__ void mma_bf16_ss(uint32_t d_tmem, uint64_t a_desc, uint64_t b_desc,
                                            uint32_t idesc, uint32_t enable) {
    asm volatile(
        "{ .reg .pred p; setp.ne.u32 p, %5, 0;\n\t"
        "tcgen05.mma.cta_group::1.kind::f16 [%0], %1, %2, %3, {%4, %4, %4, %4}, p; }"
        :: "r"(d_tmem), "l"(a_desc), "l"(b_desc), "r"(idesc), "r"(0u), "r"(enable)
        : "memory");
}
#define TCGEN05_LD_X32(r, tmem_addr) \
    asm volatile( \
        "tcgen05.ld.sync.aligned.32x32b.x32.b32 " \
        "{%0, %1, %2, %3, %4, %5, %6, %7, " \
        " %8, %9, %10, %11, %12, %13, %14, %15, " \
        " %16, %17, %18, %19, %20, %21, %22, %23, " \
        " %24, %25, %26, %27, %28, %29, %30, %31}, [%32];" \
        : "=r"((r)[0]),  "=r"((r)[1]),  "=r"((r)[2]),  "=r"((r)[3]), \
          "=r"((r)[4]),  "=r"((r)[5]),  "=r"((r)[6]),  "=r"((r)[7]), \
          "=r"((r)[8]),  "=r"((r)[9]),  "=r"((r)[10]), "=r"((r)[11]), \
          "=r"((r)[12]), "=r"((r)[13]), "=r"((r)[14]), "=r"((r)[15]), \
          "=r"((r)[16]), "=r"((r)[17]), "=r"((r)[18]), "=r"((r)[19]), \
          "=r"((r)[20]), "=r"((r)[21]), "=r"((r)[22]), "=r"((r)[23]), \
          "=r"((r)[24]), "=r"((r)[25]), "=r"((r)[26]), "=r"((r)[27]), \
          "=r"((r)[28]), "=r"((r)[29]), "=r"((r)[30]), "=r"((r)[31]) \
        : "r"(tmem_addr))
#define TC_WAIT_LD() asm volatile("tcgen05.wait::ld.sync.aligned;" ::: "memory")
#endif

// ===========================================================================
// prep kernels
// ===========================================================================
__global__ void __launch_bounds__(256)
convert_bf_kernel(const float* __restrict__ x, __nv_bfloat16* __restrict__ y, int n4)
{
    int i = blockIdx.x * blockDim.x + threadIdx.x;
    if (i >= n4) return;
    float4 v = ((const float4*)x)[i];
    ((__nv_bfloat162*)y)[2 * i]     = __nv_bfloat162(__float2bfloat16_rn(v.x), __float2bfloat16_rn(v.y));
    ((__nv_bfloat162*)y)[2 * i + 1] = __nv_bfloat162(__float2bfloat16_rn(v.z), __float2bfloat16_rn(v.w));
}

// convert 4 weight matrices in one launch (blockIdx.y selects)
__global__ void __launch_bounds__(256)
convert_w4_kernel(const float* __restrict__ w0, const float* __restrict__ w1,
                  const float* __restrict__ w2, const float* __restrict__ w3,
                  __nv_bfloat16* __restrict__ o0, __nv_bfloat16* __restrict__ o1,
                  __nv_bfloat16* __restrict__ o2, __nv_bfloat16* __restrict__ o3, int n4)
{
    int i = blockIdx.x * blockDim.x + threadIdx.x;
    if (i >= n4) return;
    const float* x = (blockIdx.y == 0) ? w0 : (blockIdx.y == 1) ? w1 : (blockIdx.y == 2) ? w2 : w3;
    __nv_bfloat16* y = (blockIdx.y == 0) ? o0 : (blockIdx.y == 1) ? o1 : (blockIdx.y == 2) ? o2 : o3;
    float4 v = ((const float4*)x)[i];
    ((__nv_bfloat162*)y)[2 * i]     = __nv_bfloat162(__float2bfloat16_rn(v.x), __float2bfloat16_rn(v.y));
    ((__nv_bfloat162*)y)[2 * i + 1] = __nv_bfloat162(__float2bfloat16_rn(v.z), __float2bfloat16_rn(v.w));
}

// ===========================================================================
// GEMM constants — 256x256 tiles, 4 accumulators in TMEM (512 cols)
// ===========================================================================
#define GM_K        DMODEL
#define CHUNK       64
#define NCHUNK      (GM_K / CHUNK)           // 16
#define BG_NSTAGE   3
#define BG_STAGE_B  65536                    // A0,A1,W0,W1 x 16KB
#define BG_SMEM     (1024 + BG_NSTAGE * BG_STAGE_B)   // 197632

static constexpr uint32_t GEMM_IDESC =
    (1u << 4) | (1u << 7) | (1u << 10) | ((128u / 8u) << 17) | ((128u / 16u) << 24);

#if HAS_TCGEN05
// 256x256 mainloop, decoupled pipeline (two alternating commit mbarriers).
__device__ __forceinline__ uint32_t
gemm256_mainloop(char* smem, uint32_t sbase,
                 const __nv_bfloat16* __restrict__ A, const __nv_bfloat16* __restrict__ W,
                 int bm, int bn, int tid)
{
    const uint32_t mbar0 = sbase + 16;
    const uint32_t mbar1 = sbase + 32;
    const int wid = tid >> 5;

    if (wid == 0) {
        asm volatile("tcgen05.alloc.cta_group::1.sync.aligned.shared::cta.b32 [%0], %1;"
                     :: "r"(sbase), "r"(512u) : "memory");
        asm volatile("tcgen05.relinquish_alloc_permit.cta_group::1.sync.aligned;" ::: "memory");
    }
    if (tid == 0) { mbar_init(mbar0, 1); mbar_init(mbar1, 1); }
    __syncthreads();
    uint32_t tmem;
    asm volatile("ld.shared.b32 %0, [%1];" : "=r"(tmem) : "r"(sbase));

    const int seg = tid & 7;
    const int r0 = tid >> 3;

    auto load_chunk = [&](int c) {
        const uint32_t st = sbase + 1024u + (uint32_t)(c % BG_NSTAGE) * BG_STAGE_B;
        const int kc = c * CHUNK;
#pragma unroll
        for (int s = 0; s < 4; ++s) {
            const int row = r0 + 32 * s;
            uint32_t boff = (uint32_t)row * 128u + (uint32_t)seg * 16u;
            uint32_t sw = boff ^ ((boff >> 3) & 0x70u);
            cp16(st + sw,           (const char*)(A + (size_t)(bm + row) * GM_K + kc) + seg * 16);
            cp16(st + 16384u + sw,  (const char*)(A + (size_t)(bm + 128 + row) * GM_K + kc) + seg * 16);
            cp16(st + 32768u + sw,  (const char*)(W + (size_t)(bn + row) * GM_K + kc) + seg * 16);
            cp16(st + 49152u + sw,  (const char*)(W + (size_t)(bn + 128 + row) * GM_K + kc) + seg * 16);
        }
        CP_COMMIT();
    };

    load_chunk(0); load_chunk(1); load_chunk(2);

    uint32_t ph0 = 0, ph1 = 0;
    for (int c = 0; c < NCHUNK; ++c) {
        if (c < NCHUNK - 1) { CP_WAIT(1); } else { CP_WAIT(0); }
        __syncthreads();
        fence_proxy_async_shared();

        if (wid == 0 && elect_one()) {
            const uint32_t st = sbase + 1024u + (uint32_t)(c % BG_NSTAGE) * BG_STAGE_B;
#pragma unroll
            for (int acc = 0; acc < 4; ++acc) {
                const int mi = acc >> 1, ni = acc & 1;
                const uint64_t da = make_desc(st + (uint32_t)mi * 16384u);
                const uint64_t dw = make_desc(st + 32768u + (uint32_t)ni * 16384u);
#pragma unroll
                for (int k = 0; k < 4; ++k)
                    mma_bf16_ss(tmem + acc * 128, da + k * 2, dw + k * 2,
                                GEMM_IDESC, (c > 0) || (k > 0));
            }
            const uint32_t mb = (c & 1) ? mbar1 : mbar0;
            asm volatile("tcgen05.commit.cta_group::1.mbarrier::arrive::one.shared::cluster.b64 [%0];"
                         :: "r"(mb) : "memory");
        }

        if (c >= 1) {
            if ((c - 1) & 1) { mbar_wait(mbar1, ph1); ph1 ^= 1; }
            else             { mbar_wait(mbar0, ph0); ph0 ^= 1; }
        }
        if (c + 2 < NCHUNK) load_chunk(c + 2);
    }

    mbar_wait(mbar1, ph1);
    asm volatile("tcgen05.fence::after_thread_sync;" ::: "memory");
    return tmem;
}

__device__ __forceinline__ void gemm256_release(uint32_t tmem, int tid)
{
    asm volatile("tcgen05.fence::before_thread_sync;" ::: "memory");
    __syncthreads();
    if ((tid >> 5) == 0)
        asm volatile("tcgen05.dealloc.cta_group::1.sync.aligned.b32 %0, %1;" :: "r"(tmem), "r"(512u));
}
#endif

// ===========================================================================
// Fused QKV GEMM: grid (12, 32); blockIdx.x>>2 selects {Wq,Wk,Wv}.
// V output is written TRANSPOSED directly into VT [bh][d][key].
// ===========================================================================
__global__ void __launch_bounds__(256)
gemm_qkv_kernel(const __nv_bfloat16* __restrict__ Xbf,
                const __nv_bfloat16* __restrict__ Wq, const __nv_bfloat16* __restrict__ Wk,
                const __nv_bfloat16* __restrict__ Wv,
                const float* __restrict__ bq, const float* __restrict__ bk,
                const float* __restrict__ bv,
                __nv_bfloat16* __restrict__ Qo, __nv_bfloat16* __restrict__ Ko,
                __nv_bfloat16* __restrict__ VT)
{
    extern __shared__ char smem[];
    const int tid = threadIdx.x;
    const int wsel = blockIdx.x >> 2;
    const int bn = (blockIdx.x & 3) * 256;
    const int bm = blockIdx.y * 256;

    const __nv_bfloat16* W = (wsel == 0) ? Wq : (wsel == 1) ? Wk : Wv;
    const float* bias      = (wsel == 0) ? bq : (wsel == 1) ? bk : bv;

#if HAS_TCGEN05
    const uint32_t sbase = smem_u32(smem);
    const uint32_t tmem = gemm256_mainloop(smem, sbase, Xbf, W, bm, bn, tid);

    const int wid = tid >> 5, lid = tid & 31;
    const int sub = wid & 3;
    const int colblk = (wid >> 2) * 64;

    if (wsel < 2) {
        __nv_bfloat16* Chi = (wsel == 0) ? Qo : Ko;
#pragma unroll
        for (int acc = 0; acc < 4; ++acc) {
            const int mi = acc >> 1, ni = acc & 1;
            const int row = bm + mi * 128 + sub * 32 + lid;
            __nv_bfloat16* hrow = Chi + (size_t)row * DMODEL + bn + ni * 128;
#pragma unroll
            for (int cb = 0; cb < 64; cb += 32) {
                const int c0 = colblk + cb;
                uint32_t dr[32];
                TCGEN05_LD_X32(dr, tmem + acc * 128 + c0);
                TC_WAIT_LD();
                const float* brow = bias + bn + ni * 128 + c0;
#pragma unroll
                for (int j = 0; j < 32; j += 4) {
                    float vx = __uint_as_float(dr[j + 0]) + brow[j + 0];
                    float vy = __uint_as_float(dr[j + 1]) + brow[j + 1];
                    float vz = __uint_as_float(dr[j + 2]) + brow[j + 2];
                    float vw = __uint_as_float(dr[j + 3]) + brow[j + 3];
                    *(__nv_bfloat162*)(hrow + c0 + j)     = __nv_bfloat162(
                        __float2bfloat16_rn(vx), __float2bfloat16_rn(vy));
                    *(__nv_bfloat162*)(hrow + c0 + j + 2) = __nv_bfloat162(
                        __float2bfloat16_rn(vz), __float2bfloat16_rn(vw));
                }
            }
        }
    } else {
        // V: write transposed (coalesced 64B warp segments along `key`).
#pragma unroll
        for (int acc = 0; acc < 4; ++acc) {
            const int mi = acc >> 1, ni = acc & 1;
            const int row = bm + mi * 128 + sub * 32 + lid;   // global token
            const int b   = row >> 11;
            const int key = row & (SEQ - 1);
#pragma unroll
            for (int cb = 0; cb < 64; cb += 32) {
                const int c0 = colblk + cb;
                uint32_t dr[32];
                TCGEN05_LD_X32(dr, tmem + acc * 128 + c0);
                TC_WAIT_LD();
                const int colbase = bn + ni * 128 + c0;
#pragma unroll
                for (int j = 0; j < 32; j++) {
                    const int col = colbase + j;
                    const int hh = col >> 6, d = col & 63;
                    VT[((size_t)(b * NHEAD + hh) * HDIM + d) * SEQ + key] =
                        __float2bfloat16_rn(__uint_as_float(dr[j]) + bias[col]);
                }
            }
        }
    }
    gemm256_release(tmem, tid);

#else  // SIMT fallback: 4x sequential 128x128 blocks
    float* As = (float*)smem;
    float* Ws = (float*)(smem + 8192);
    const int tr = tid >> 4, tc = tid & 15;
    const int lrow = tid >> 1, lk0 = (tid & 1) * 8;
    for (int mi = 0; mi < 2; mi++)
    for (int ni = 0; ni < 2; ni++) {
        const int bm2 = bm + mi * 128, bn2 = bn + ni * 128;
        float acc[8][8];
#pragma unroll
        for (int i = 0; i < 8; i++)
#pragma unroll
            for (int j = 0; j < 8; j++) acc[i][j] = 0.f;
        for (int k0 = 0; k0 < GM_K; k0 += 16) {
            __syncthreads();
            {
                const __nv_bfloat162* ah = (const __nv_bfloat162*)(Xbf + (size_t)(bm2 + lrow) * GM_K + k0 + lk0);
                const __nv_bfloat162* wh = (const __nv_bfloat162*)(W + (size_t)(bn2 + lrow) * GM_K + k0 + lk0);
#pragma unroll
                for (int p = 0; p < 4; p++) {
                    float2 h = __bfloat1622float2(ah[p]);
                    As[(lk0 + 2 * p) * 128 + lrow]     = h.x;
                    As[(lk0 + 2 * p + 1) * 128 + lrow] = h.y;
                    float2 w2 = __bfloat1622float2(wh[p]);
                    Ws[(lk0 + 2 * p) * 128 + lrow]     = w2.x;
                    Ws[(lk0 + 2 * p + 1) * 128 + lrow] = w2.y;
                }
            }
            __syncthreads();
#pragma unroll
            for (int k = 0; k < 16; k++) {
                float b2[8], a2[8];
#pragma unroll
                for (int j = 0; j < 8; j++) b2[j] = Ws[k * 128 + tc * 8 + j];
#pragma unroll
                for (int i = 0; i < 8; i++) a2[i] = As[k * 128 + tr * 8 + i];
#pragma unroll
                for (int i = 0; i < 8; i++)
#pragma unroll
                    for (int j = 0; j < 8; j++) acc[i][j] += a2[i] * b2[j];
            }
        }
#pragma unroll
        for (int i = 0; i < 8; i++) {
            const int row = bm2 + tr * 8 + i;
#pragma unroll
            for (int j = 0; j < 8; j++) {
                const int col = bn2 + tc * 8 + j;
                __nv_bfloat16 v = __float2bfloat16_rn(acc[i][j] + bias[col]);
                if (wsel == 0)      Qo[(size_t)row * DMODEL + col] = v;
                else if (wsel == 1) Ko[(size_t)row * DMODEL + col] = v;
                else {
                    const int b = row >> 11, key = row & (SEQ - 1);
                    const int hh = col >> 6, d = col & 63;
                    VT[((size_t)(b * NHEAD + hh) * HDIM + d) * SEQ + key] = v;
                }
            }
        }
        __syncthreads();
    }
#endif
}

// ===========================================================================
// Wo GEMM: Y = AObf @ Wob^T + bo + X.  256x256 tile, fp32 out.  grid (4, 32).
// ===========================================================================
__global__ void __launch_bounds__(256)
gemm_wo_kernel(const __nv_bfloat16* __restrict__ A, const __nv_bfloat16* __restrict__ W,
               const float* __restrict__ bias, const float* __restrict__ resid,
               float* __restrict__ C)
{
    extern __shared__ char smem[];
    const int tid = threadIdx.x;
    const int bn = blockIdx.x * 256;
    const int bm = blockIdx.y * 256;

#if HAS_TCGEN05
    const uint32_t sbase = smem_u32(smem);
    const uint32_t tmem = gemm256_mainloop(smem, sbase, A, W, bm, bn, tid);

    const int wid = tid >> 5, lid = tid & 31;
    const int sub = wid & 3;
    const int colblk = (wid >> 2) * 64;
#pragma unroll
    for (int acc = 0; acc < 4; ++acc) {
        const int mi = acc >> 1, ni = acc & 1;
        const int row = bm + mi * 128 + sub * 32 + lid;
        float* crow = C + (size_t)row * DMODEL + bn + ni * 128;
        const float* rrow = resid + (size_t)row * DMODEL + bn + ni * 128;
        const float* brow0 = bias + bn + ni * 128;
#pragma unroll
        for (int cb = 0; cb < 64; cb += 32) {
            const int c0 = colblk + cb;
            uint32_t dr[32];
            TCGEN05_LD_X32(dr, tmem + acc * 128 + c0);
            TC_WAIT_LD();
#pragma unroll
            for (int j = 0; j < 32; j += 4) {
                float4 r = *(const float4*)(rrow + c0 + j);
                float4 v;
                v.x = __uint_as_float(dr[j + 0]) + brow0[c0 + j + 0] + r.x;
                v.y = __uint_as_float(dr[j + 1]) + brow0[c0 + j + 1] + r.y;
                v.z = __uint_as_float(dr[j + 2]) + brow0[c0 + j + 2] + r.z;
                v.w = __uint_as_float(dr[j + 3]) + brow0[c0 + j + 3] + r.w;
                *(float4*)(crow + c0 + j) = v;
            }
        }
    }
    gemm256_release(tmem, tid);

#else  // SIMT fallback: 4x sequential 128x128 blocks
    float* As = (float*)smem;
    float* Ws = (float*)(smem + 8192);
    const int tr = tid >> 4, tc = tid & 15;
    const int lrow = tid >> 1, lk0 = (tid & 1) * 8;
    for (int mi = 0; mi < 2; mi++)
    for (int ni = 0; ni < 2; ni++) {
        const int bm2 = bm + mi * 128, bn2 = bn + ni * 128;
        float acc[8][8];
#pragma unroll
        for (int i = 0; i < 8; i++)
#pragma unroll
            for (int j = 0; j < 8; j++) acc[i][j] = 0.f;
        for (int k0 = 0; k0 < GM_K; k0 += 16) {
            __syncthreads();
            {
                const __nv_bfloat162* ah = (const __nv_bfloat162*)(A + (size_t)(bm2 + lrow) * GM_K + k0 + lk0);
                const __nv_bfloat162* wh = (const __nv_bfloat162*)(W + (size_t)(bn2 + lrow) * GM_K + k0 + lk0);
#pragma unroll
                for (int p = 0; p < 4; p++) {
                    float2 h = __bfloat1622float2(ah[p]);
                    As[(lk0 + 2 * p) * 128 + lrow]     = h.x;
                    As[(lk0 + 2 * p + 1) * 128 + lrow] = h.y;
                    float2 w2 = __bfloat1622float2(wh[p]);
                    Ws[(lk0 + 2 * p) * 128 + lrow]     = w2.x;
                    Ws[(lk0 + 2 * p + 1) * 128 + lrow] = w2.y;
                }
            }
            __syncthreads();
#pragma unroll
            for (int k = 0; k < 16; k++) {
                float b2[8], a2[8];
#pragma unroll
                for (int j = 0; j < 8; j++) b2[j] = Ws[k * 128 + tc * 8 + j];
#pragma unroll
                for (int i = 0; i < 8; i++) a2[i] = As[k * 128 + tr * 8 + i];
#pragma unroll
                for (int i = 0; i < 8; i++)
#pragma unroll
                    for (int j = 0; j < 8; j++) acc[i][j] += a2[i] * b2[j];
            }
        }
#pragma unroll
        for (int i = 0; i < 8; i++) {
            const int row = bm2 + tr * 8 + i;
#pragma unroll
            for (int j = 0; j < 8; j++) {
                const int col = bn2 + tc * 8 + j;
                C[(size_t)row * DMODEL + col] =
                    acc[i][j] + bias[col] + resid[(size_t)row * DMODEL + col];
            }
        }
        __syncthreads();
    }
#endif
}

// ===========================================================================
// Attention: 256 threads; warp pairs split the 128 S-columns.
// LDTM-first schedule: S is consumed (into regs) before sync#1, then warp0
// issues QK(j+1) which overlaps exp/pack/store.  K double-buffered,
// VT single-buffered (prefetched after the PV(j-1) wait).
// ===========================================================================
#define AT_OFF_Q    1024
#define AT_OFF_K    (AT_OFF_Q + 16384)       // 2 x 16KB buffers
#define AT_OFF_VT   (AT_OFF_K + 32768)       // single 16KB buffer
#define AT_OFF_P    (AT_OFF_VT + 16384)      // 32KB
#define ATTN_SMEM   (AT_OFF_P + 32768)       // 99328

#define EXP_SCALE2  0.18033688011112042f     // 0.125 * log2(e)
#define EXP_SHIFT2  8.656170245333781f       // 6.0  * log2(e)

static constexpr uint32_t IDESC_QK =
    (1u << 4) | (1u << 7) | (1u << 10) | (16u << 17) | (8u << 24);   // M=128,N=128
static constexpr uint32_t IDESC_PV =
    (1u << 4) | (1u << 7) | (1u << 10) | (8u << 17) | (8u << 24);    // M=128,N=64

__global__ void __launch_bounds__(256, 2)
attn_kernel(const __nv_bfloat16* __restrict__ Qhi, const __nv_bfloat16* __restrict__ Kbf,
            const __nv_bfloat16* __restrict__ VT, __nv_bfloat16* __restrict__ AObf)
{
    extern __shared__ char smem[];
    const int tid = threadIdx.x;
    const int qtile = blockIdx.x;
    const int bh = blockIdx.y;
    const int b = bh >> 4, h = bh & 15;

#if HAS_TCGEN05
    const uint32_t sbase = smem_u32(smem);
    const uint32_t mbarQK = sbase + 16;
    const uint32_t mbarPV = sbase + 32;
    const int wid = tid >> 5;
    const int half = wid >> 2;

    if (wid == 0) {
        asm volatile("tcgen05.alloc.cta_group::1.sync.aligned.shared::cta.b32 [%0], %1;"
                     :: "r"(sbase), "r"(256u) : "memory");
        asm volatile("tcgen05.relinquish_alloc_permit.cta_group::1.sync.aligned;" ::: "memory");
    }
    if (tid == 0) { mbar_init(mbarQK, 1); mbar_init(mbarPV, 1); }
    __syncthreads();
    uint32_t tmem;
    asm volatile("ld.shared.b32 %0, [%1];" : "=r"(tmem) : "r"(sbase));
    const uint32_t tmem_S = tmem;
    const uint32_t tmem_O = tmem + 128;

    // ---- prologue: load Q + K(0) + K(1) ----
    {
        const int row = tid >> 1, s0 = (tid & 1) * 4;
        const char* gq  = (const char*)(Qhi + (size_t)(b * SEQ + qtile * 128 + row) * DMODEL + h * HDIM);
        const char* gk0 = (const char*)(Kbf + (size_t)(b * SEQ + row) * DMODEL + h * HDIM);
        const char* gk1 = (const char*)(Kbf + (size_t)(b * SEQ + 128 + row) * DMODEL + h * HDIM);
#pragma unroll
        for (int c = 0; c < 4; c++) {
            const int seg = s0 + c;
            uint32_t boff = (uint32_t)row * 128u + (uint32_t)seg * 16u;
            uint32_t sw = boff ^ ((boff >> 3) & 0x70u);
            cp16(sbase + AT_OFF_Q + sw, gq + seg * 16);
            cp16(sbase + AT_OFF_K + sw, gk0 + seg * 16);
            cp16(sbase + AT_OFF_K + 16384u + sw, gk1 + seg * 16);
        }
        CP_COMMIT();
        CP_WAIT(0);
    }
    fence_proxy_async_shared();
    __syncthreads();

    const uint64_t dq = make_desc(sbase + AT_OFF_Q);
    if (wid == 0 && elect_one()) {
        const uint64_t dk = make_desc(sbase + AT_OFF_K);
#pragma unroll
        for (int k = 0; k < 4; ++k)
            mma_bf16_ss(tmem_S, dq + k * 2, dk + k * 2, IDESC_QK, k > 0);
        asm volatile("tcgen05.commit.cta_group::1.mbarrier::arrive::one.shared::cluster.b64 [%0];"
                     :: "r"(mbarQK) : "memory");
    }

    float l = 0.f;
    uint32_t phQK = 0, phPV = 0;
    const int rowp = tid & 127;
    const int g0 = half * 2;

    for (int j = 0; j < SEQ / 128; ++j) {
        // ---- 1. QK(j) done -> S readable; K[j&1] consumed ----
        mbar_wait(mbarQK, phQK); phQK ^= 1;
        asm volatile("tcgen05.fence::after_thread_sync;" ::: "memory");

        // early prefetch of K(j+2) into K[j&1]
        if (j + 2 < SEQ / 128) {
            const uint32_t kb = AT_OFF_K + ((uint32_t)j & 1u) * 16384u;
            const int row = tid >> 1, s0 = (tid & 1) * 4;
            const char* gk = (const char*)(Kbf + (size_t)(b * SEQ + (j + 2) * 128 + row) * DMODEL + h * HDIM);
#pragma unroll
            for (int c = 0; c < 4; c++) {
                const int seg = s0 + c;
                uint32_t boff = (uint32_t)row * 128u + (uint32_t)seg * 16u;
                uint32_t sw = boff ^ ((boff >> 3) & 0x70u);
                cp16(sbase + kb + sw, gk + seg * 16);
            }
            CP_COMMIT();
        }

        // ---- 2. drain S into registers (both groups) ----
        uint32_t t0[32], t1[32];
        TCGEN05_LD_X32(t0, tmem_S + g0 * 32);
        TCGEN05_LD_X32(t1, tmem_S + (g0 + 1) * 32);
        TC_WAIT_LD();
        asm volatile("tcgen05.fence::before_thread_sync;" ::: "memory");
        __syncthreads();                 // #1: all warps drained S

        // ---- 3. warp0: issue QK(j+1) immediately (overlaps exp below) ----
        if (wid == 0 && elect_one()) {
            if (j + 1 < SEQ / 128) {
                asm volatile("tcgen05.fence::after_thread_sync;" ::: "memory");
                const uint64_t dk = make_desc(sbase + AT_OFF_K + ((uint32_t)(j + 1) & 1u) * 16384u);
#pragma unroll
                for (int k = 0; k < 4; ++k)
                    mma_bf16_ss(tmem_S, dq + k * 2, dk + k * 2, IDESC_QK, k > 0);
                asm volatile("tcgen05.commit.cta_group::1.mbarrier::arrive::one.shared::cluster.b64 [%0];"
                             :: "r"(mbarQK) : "memory");
            }
        }

        // ---- 4. exp/pack (overlapping QK(j+1)) ----
        float lsum = 0.f;
        uint32_t pkk0[16], pkk1[16];
#pragma unroll
        for (int i = 0; i < 16; i++) {
            float p0 = fast_ex2(fmaf(__uint_as_float(t0[2 * i]),     EXP_SCALE2, -EXP_SHIFT2));
            float p1 = fast_ex2(fmaf(__uint_as_float(t0[2 * i + 1]), EXP_SCALE2, -EXP_SHIFT2));
            lsum += p0 + p1;
            __nv_bfloat162 pb = __floats2bfloat162_rn(p0, p1);
            pkk0[i] = *(uint32_t*)&pb;
        }
#pragma unroll
        for (int i = 0; i < 16; i++) {
            float p0 = fast_ex2(fmaf(__uint_as_float(t1[2 * i]),     EXP_SCALE2, -EXP_SHIFT2));
            float p1 = fast_ex2(fmaf(__uint_as_float(t1[2 * i + 1]), EXP_SCALE2, -EXP_SHIFT2));
            lsum += p0 + p1;
            __nv_bfloat162 pb = __floats2bfloat162_rn(p0, p1);
            pkk1[i] = *(uint32_t*)&pb;
        }
        l += lsum;

        // ---- 5. PV(j-1) done -> VT + P buffers free ----
        if (j > 0) { mbar_wait(mbarPV, phPV); phPV ^= 1; }

        // prefetch VT(j) (single buffer)
        {
            const int d = tid >> 2, q4 = tid & 3;
            const char* vs = (const char*)(VT + ((size_t)bh * HDIM + d) * SEQ + j * 128);
#pragma unroll
            for (int c = 0; c < 4; c++) {
                const int key = q4 * 32 + c * 8;
                uint32_t atom = (uint32_t)(d >> 3) + (uint32_t)(key >> 6) * 8u;
                uint32_t boff = atom * 1024u + (uint32_t)(d & 7) * 128u + (uint32_t)(key & 63) * 2u;
                uint32_t sw = boff ^ ((boff >> 3) & 0x70u);
                cp16(sbase + AT_OFF_VT + sw, vs + key * 2);
            }
            CP_COMMIT();
        }

        // store P (both groups)
#pragma unroll
        for (int s = 0; s < 4; s++) {
            const int col = g0 * 32 + s * 8;
            uint32_t atom = (uint32_t)(rowp >> 3) + (uint32_t)(col >> 6) * 16u;
            uint32_t boff = atom * 1024u + (uint32_t)(rowp & 7) * 128u + (uint32_t)(col & 63) * 2u;
            uint32_t sw = boff ^ ((boff >> 3) & 0x70u);
            *(uint4*)(smem + AT_OFF_P + sw) =
                make_uint4(pkk0[4 * s], pkk0[4 * s + 1], pkk0[4 * s + 2], pkk0[4 * s + 3]);
        }
#pragma unroll
        for (int s = 0; s < 4; s++) {
            const int col = (g0 + 1) * 32 + s * 8;
            uint32_t atom = (uint32_t)(rowp >> 3) + (uint32_t)(col >> 6) * 16u;
            uint32_t boff = atom * 1024u + (uint32_t)(rowp & 7) * 128u + (uint32_t)(col & 63) * 2u;
            uint32_t sw = boff ^ ((boff >> 3) & 0x70u);
            *(uint4*)(smem + AT_OFF_P + sw) =
                make_uint4(pkk1[4 * s], pkk1[4 * s + 1], pkk1[4 * s + 2], pkk1[4 * s + 3]);
        }

        // ---- 6. all async loads landed; PV(j) ----
        CP_WAIT(0);
        fence_proxy_async_shared();
        __syncthreads();                 // #2

        if (wid == 0 && elect_one()) {
            const uint64_t dp = make_desc(sbase + AT_OFF_P);
            const uint64_t dv = make_desc(sbase + AT_OFF_VT);
#pragma unroll
            for (int st = 0; st < 8; ++st) {
                uint64_t po = (st < 4) ? (uint64_t)(st * 2) : (uint64_t)(1024 + (st - 4) * 2);
                uint64_t vo = (st < 4) ? (uint64_t)(st * 2) : (uint64_t)(512 + (st - 4) * 2);
                mma_bf16_ss(tmem_O, dp + po, dv + vo, IDESC_PV, (j > 0) || (st > 0));
            }
            asm volatile("tcgen05.commit.cta_group::1.mbarrier::arrive::one.shared::cluster.b64 [%0];"
                         :: "r"(mbarPV) : "memory");
        }
    }

    // ---- epilogue: PV(15) done, read O once, normalize ----
    mbar_wait(mbarPV, phPV);
    asm volatile("tcgen05.fence::after_thread_sync;" ::: "memory");

    float* lpart = (float*)(smem + AT_OFF_P);
    lpart[tid] = l;
    __syncthreads();

    if (tid < 128) {
        const float inv = 1.f / (lpart[tid] + lpart[tid + 128]);
        const size_t orow = (size_t)(b * SEQ + qtile * 128 + tid) * DMODEL + h * HDIM;
#pragma unroll
        for (int g = 0; g < 2; g++) {
            uint32_t orr[32];
            TCGEN05_LD_X32(orr, tmem_O + g * 32);
            TC_WAIT_LD();
#pragma unroll
            for (int i = 0; i < 16; i++) {
                float v0 = __uint_as_float(orr[2 * i]) * inv;
                float v1 = __uint_as_float(orr[2 * i + 1]) * inv;
                *(__nv_bfloat162*)(AObf + orow + g * 32 + 2 * i) = __nv_bfloat162(
                    __float2bfloat16_rn(v0), __float2bfloat16_rn(v1));
            }
        }
    }
    asm volatile("tcgen05.fence::before_thread_sync;" ::: "memory");
    __syncthreads();
    if (wid == 0)
        asm volatile("tcgen05.dealloc.cta_group::1.sync.aligned.b32 %0, %1;" :: "r"(tmem), "r"(256u));

#else  // ---------------- SIMT fallback (bf16 inputs; correctness-only) ----
    float* Ks = (float*)smem;
    float* Vs = Ks + 64 * 64;
    const int qrow = qtile * 128 + (tid & 127);

    float q[64], o[64];
    if (tid < 128) {
        const __nv_bfloat162* qp = (const __nv_bfloat162*)
            (Qhi + (size_t)(b * SEQ + qrow) * DMODEL + h * HDIM);
#pragma unroll
        for (int i = 0; i < 32; i++) {
            float2 t = __bfloat1622float2(qp[i]);
            q[2 * i] = t.x; q[2 * i + 1] = t.y;
        }
#pragma unroll
        for (int i = 0; i < 64; i++) o[i] = 0.f;
    }

    float m = -1e30f, l = 0.f;
    for (int j0 = 0; j0 < SEQ; j0 += 64) {
        __syncthreads();
        for (int i = tid; i < 64 * 32; i += 256) {
            const int r = i >> 5, c2 = i & 31;
            __nv_bfloat162 kv = ((const __nv_bfloat162*)
                (Kbf + (size_t)(b * SEQ + j0 + r) * DMODEL + h * HDIM))[c2];
            float2 kf = __bfloat1622float2(kv);
            Ks[r * 64 + 2 * c2] = kf.x; Ks[r * 64 + 2 * c2 + 1] = kf.y;
        }
        for (int i = tid; i < 64 * 64; i += 256) {
            const int r = i >> 6, d = i & 63;
            Vs[r * 64 + d] = __bfloat162float(VT[((size_t)bh * HDIM + d) * SEQ + j0 + r]);
        }
        __syncthreads();

        if (tid < 128) {
            for (int j = 0; j < 64; j++) {
                float s = 0.f;
#pragma unroll
                for (int d = 0; d < 64; d++) s += q[d] * Ks[j * 64 + d];
                s *= 0.125f;
                if (s > m) {
                    float c = __expf(m - s);
                    l *= c;
#pragma unroll
                    for (int d = 0; d < 64; d++) o[d] *= c;
                    m = s;
                }
                float p = __expf(s - m);
                l += p;
#pragma unroll
                for (int d = 0; d < 64; d++) o[d] += p * Vs[j * 64 + d];
            }
        }
    }

    if (tid < 128) {
        const float inv = 1.f / l;
        __nv_bfloat162* op = (__nv_bfloat162*)(AObf + (size_t)(b * SEQ + qrow) * DMODEL + h * HDIM);
#pragma unroll
        for (int i = 0; i < 32; i++)
            op[i] = __nv_bfloat162(__float2bfloat16_rn(o[2 * i] * inv),
                                   __float2bfloat16_rn(o[2 * i + 1] * inv));
    }
#endif
}

// ===========================================================================
// LayerNorm over rows of 1024
// ===========================================================================
__global__ void __launch_bounds__(256)
ln_kernel(const float* __restrict__ Y, const float* __restrict__ gamma,
          const float* __restrict__ beta, float* __restrict__ out)
{
    __shared__ float red[8];
    __shared__ float bcast;

    const int row = blockIdx.x;
    const int tid = threadIdx.x;
    const float4 v = ((const float4*)(Y + (size_t)row * DMODEL))[tid];

    float s = v.x + v.y + v.z + v.w;
#pragma unroll
    for (int off = 16; off; off >>= 1) s += __shfl_xor_sync(0xffffffffu, s, off);
    if ((tid & 31) == 0) red[tid >> 5] = s;
    __syncthreads();
    if (tid == 0) {
        float t = 0.f;
#pragma unroll
        for (int i = 0; i < 8; i++) t += red[i];
        bcast = t * (1.f / 1024.f);
    }
    __syncthreads();
    const float mean = bcast;

    const float dx = v.x - mean, dy = v.y - mean, dz = v.z - mean, dw = v.w - mean;
    float ss = dx * dx + dy * dy + dz * dz + dw * dw;
#pragma unroll
    for (int off = 16; off; off >>= 1) ss += __shfl_xor_sync(0xffffffffu, ss, off);
    __syncthreads();
    if ((tid & 31) == 0) red[tid >> 5] = ss;
    __syncthreads();
    if (tid == 0) {
        float t = 0.f;
#pragma unroll
        for (int i = 0; i < 8; i++) t += red[i];
        bcast = rsqrtf(t * (1.f / 1024.f) + 1e-12f);
    }
    __syncthreads();
    const float inv = bcast;

    const float4 g = ((const float4*)gamma)[tid];
    const float4 bb = ((const float4*)beta)[tid];
    float4 o = make_float4(dx * inv * g.x + bb.x, dy * inv * g.y + bb.y,
                           dz * inv * g.z + bb.z, dw * inv * g.w + bb.w);
    ((float4*)(out + (size_t)row * DMODEL))[tid] = o;
}

// ===========================================================================
extern "C" void kernel_launch(void* const* d_in, const int* in_sizes, int n_in,
                              void* d_out, int out_size)
{
    const float* X     = (const float*)d_in[0];
    const float* Wq    = (const float*)d_in[1];
    const float* bq    = (const float*)d_in[2];
    const float* Wk    = (const float*)d_in[3];
    const float* bk    = (const float*)d_in[4];
    const float* Wv    = (const float*)d_in[5];
    const float* bv    = (const float*)d_in[6];
    const float* Wo    = (const float*)d_in[7];
    const float* bo    = (const float*)d_in[8];
    const float* gamma = (const float*)d_in[9];
    const float* beta  = (const float*)d_in[10];
    float* out = (float*)d_out;

    float* Yb;
    __nv_bfloat16 *Xbf, *AObf, *Qhi, *Kbf, *VTb, *Wqb, *Wkb, *Wvb, *Wob;
    cudaGetSymbolAddress((void**)&Yb, g_Y);
    cudaGetSymbolAddress((void**)&Xbf, g_Xbf);
    cudaGetSymbolAddress((void**)&AObf, g_AObf);
    cudaGetSymbolAddress((void**)&Qhi, g_Qhi);
    cudaGetSymbolAddress((void**)&Kbf, g_Kbf);
    cudaGetSymbolAddress((void**)&VTb, g_VT);
    cudaGetSymbolAddress((void**)&Wqb, g_Wqb);
    cudaGetSymbolAddress((void**)&Wkb, g_Wkb);
    cudaGetSymbolAddress((void**)&Wvb, g_Wvb);
    cudaGetSymbolAddress((void**)&Wob, g_Wob);

    cudaFuncSetAttribute(gemm_qkv_kernel, cudaFuncAttributeMaxDynamicSharedMemorySize, BG_SMEM);
    cudaFuncSetAttribute(gemm_wo_kernel, cudaFuncAttributeMaxDynamicSharedMemorySize, BG_SMEM);
    cudaFuncSetAttribute(attn_kernel, cudaFuncAttributeMaxDynamicSharedMemorySize, ATTN_SMEM);

    const int nX4 = ROWS * DMODEL / 4;
    const int nW4 = DMODEL * DMODEL / 4;

    convert_bf_kernel<<<(nX4 + 255) / 256, 256>>>(X, Xbf, nX4);                       // 0
    convert_w4_kernel<<<dim3((nW4 + 255) / 256, 4), 256>>>(
        Wq, Wk, Wv, Wo, Wqb, Wkb, Wvb, Wob, nW4);                                     // 1

    gemm_qkv_kernel<<<dim3(12, ROWS / 256), 256, BG_SMEM>>>(
        Xbf, Wqb, Wkb, Wvb, bq, bk, bv, Qhi, Kbf, VTb);                               // 2

    attn_kernel<<<dim3(SEQ / 128, BATCH * NHEAD), 256, ATTN_SMEM>>>(Qhi, Kbf, VTb, AObf); // 3

    gemm_wo_kernel<<<dim3(DMODEL / 256, ROWS / 256), 256, BG_SMEM>>>(AObf, Wob, bo, X, Yb); // 4

    ln_kernel<<<ROWS, 256>>>(Yb, gamma, beta, out);                                   // 5
}